// round 16
// baseline (speedup 1.0000x reference)
#include <cuda_runtime.h>
#include <cuda_bf16.h>
#include <cuda_fp16.h>
#include <math.h>

#define N_NODES 50000
#define N_EDGES 400000
#define SLOPE   0.2f

#define ETILE   64
#define NTILES  (N_EDGES / ETILE)   // 6250, exact
#define NSCANB  196                 // ceil(50000/256)
#define NBLK64  782                 // ceil(50000/64) tiles per type bucket
#define PERM3_CAP (NBLK64 * 64)     // 50048

// ---------------- scratch ----------------
__device__ __align__(16) float g_P[(size_t)N_NODES * 128];
__device__ __align__(16) float g_star[N_NODES * 8];
__device__ __align__(16) float g_ssrc[N_NODES * 8];
__device__ __align__(16) __half g_attrpart_h[(size_t)N_EDGES * 128];  // CSR-ordered
__device__ __align__(16) float g_ex[N_EDGES * 8];                     // CSR-ordered
__device__ __align__(16) float g_denom[N_NODES * 8];
__device__ int g_src[N_EDGES], g_tar[N_EDGES];
__device__ int g_deg[N_NODES], g_off[N_NODES + 1], g_cursor[N_NODES];
__device__ int g_perm3[3 * PERM3_CAP];
__device__ int g_tcursor3[3];
// single-pass scan state
__device__ volatile int g_agg[NSCANB], g_pre[NSCANB], g_flag[NSCANB];

// mma-ready packed B fragments, CONTIGUOUS per (warp-group, kstep)
__device__ __align__(16) uint4 gBea[16 * 4 * 32];
__device__ __align__(16) uint4 gBet[16 * 4 * 32];
__device__ __align__(16) uint4 gBup[16 * 8 * 32];
__device__ __align__(16) uint4 gBa [16 * 32];
__device__ __align__(16) uint4 gBn [3 * 16 * 16 * 32];
__device__ __align__(16) uint4 gBuT[16 * 8 * 32];
__device__ __align__(16) uint4 gBs [2 * 8 * 32];

__device__ __forceinline__ float lrelu(float x) { return x >= 0.f ? x : SLOPE * x; }

__device__ __forceinline__ void splitpack(float x, float y, unsigned& hi, unsigned& lo) {
    __nv_bfloat16 hx = __float2bfloat16(x);
    __nv_bfloat16 hy = __float2bfloat16(y);
    float lx = x - __bfloat162float(hx);
    float ly = y - __bfloat162float(hy);
    __nv_bfloat162 h2 = __halves2bfloat162(hx, hy);
    __nv_bfloat162 l2 = __halves2bfloat162(__float2bfloat16(lx), __float2bfloat16(ly));
    hi = *reinterpret_cast<unsigned*>(&h2);
    lo = *reinterpret_cast<unsigned*>(&l2);
}

__device__ __forceinline__ uint4 pack4(float w0, float w1, float w2, float w3) {
    unsigned h0, l0, h1, l1;
    splitpack(w0, w1, h0, l0);
    splitpack(w2, w3, h1, l1);
    return make_uint4(h0, h1, l0, l1);
}

__device__ __forceinline__ void mma16816(float* c, unsigned a0, unsigned a1, unsigned a2,
                                         unsigned a3, unsigned b0, unsigned b1) {
    asm volatile(
        "mma.sync.aligned.m16n8k16.row.col.f32.bf16.bf16.f32 "
        "{%0,%1,%2,%3}, {%4,%5,%6,%7}, {%8,%9}, {%0,%1,%2,%3};"
        : "+f"(c[0]), "+f"(c[1]), "+f"(c[2]), "+f"(c[3])
        : "r"(a0), "r"(a1), "r"(a2), "r"(a3), "r"(b0), "r"(b1));
}

__device__ __forceinline__ void ldsm4(unsigned& r0, unsigned& r1, unsigned& r2, unsigned& r3,
                                      unsigned addr) {
    asm volatile("ldmatrix.sync.aligned.m8n8.x4.shared.b16 {%0,%1,%2,%3}, [%4];"
                 : "=r"(r0), "=r"(r1), "=r"(r2), "=r"(r3) : "r"(addr));
}

// ---------------- zeroing (no reads; runs first) ----------------
__global__ void k_zero() {
    int i = blockIdx.x * blockDim.x + threadIdx.x;
    if (i < N_NODES * 8) g_denom[i] = 0.f;
    if (i < N_NODES) g_deg[i] = 0;
    if (i < 3 * PERM3_CAP) g_perm3[i] = -1;
    if (i < 3) g_tcursor3[i] = 0;
    if (i < NSCANB) g_flag[i] = 0;
}

// ---------------- fused init: edge copy + hist + bucket scatter + weight pack ----------------
__global__ void k_init(const int* __restrict__ eidx, const int* __restrict__ ntl,
                       const float* __restrict__ Wea, const float* __restrict__ Wet,
                       const float* __restrict__ Wupd, const float* __restrict__ Wattn,
                       const float* __restrict__ Wn) {
    int i = blockIdx.x * blockDim.x + threadIdx.x;
    if (i < N_EDGES) {
        int s = eidx[i];
        g_src[i] = s;
        g_tar[i] = eidx[N_EDGES + i];
        atomicAdd(&g_deg[s], 1);
    }
    if (i < N_NODES) {
        int tp = ntl[i];
        int p = atomicAdd(&g_tcursor3[tp], 1);
        g_perm3[tp * PERM3_CAP + p] = i;
    }

    if (i < 2048) {
        int fc = i & 3, fr = (i >> 2) & 7, kk = (i >> 5) & 3, g = i >> 7;
        int n = (g >> 2) * 32 + (g & 3) * 8 + fr;
        int k0 = 2 * (kk * 8 + fc);
        gBea[i] = pack4(Wea[k0 * 128 + n],       Wea[(k0 + 1) * 128 + n],
                        Wea[(k0 + 8) * 128 + n], Wea[(k0 + 9) * 128 + n]);
        gBet[i] = pack4(Wet[k0 * 128 + n],       Wet[(k0 + 1) * 128 + n],
                        Wet[(k0 + 8) * 128 + n], Wet[(k0 + 9) * 128 + n]);
    }
    if (i < 4096) {
        int fc = i & 3, fr = (i >> 2) & 7, kk = (i >> 5) & 7, g = i >> 8;
        int n = (g >> 2) * 32 + (g & 3) * 8 + fr;
        int k0 = 2 * (kk * 8 + fc);
        gBup[i] = pack4(Wupd[(128 + k0) * 128 + n], Wupd[(129 + k0) * 128 + n],
                        Wupd[(136 + k0) * 128 + n], Wupd[(137 + k0) * 128 + n]);
        gBuT[i] = pack4(Wupd[k0 * 128 + n],       Wupd[(k0 + 1) * 128 + n],
                        Wupd[(k0 + 8) * 128 + n], Wupd[(k0 + 9) * 128 + n]);
    }
    if (i < 512) {
        int fc = i & 3, fr = (i >> 2) & 7, kk = i >> 5;
        int k0 = 2 * (kk * 8 + fc);
        int h = fr;
        gBa[i] = pack4(Wattn[(128 + k0) * 8 + h], Wattn[(129 + k0) * 8 + h],
                       Wattn[(136 + k0) * 8 + h], Wattn[(137 + k0) * 8 + h]);
        int j = i >> 8, kk2 = (i >> 5) & 7;
        int n = j * 8 + fr;
        int q0 = 2 * (kk2 * 8 + fc);
        int ro = (n < 8) ? 0 : 384;
        int hh = (n < 8) ? n : n - 8;
        gBs[i] = pack4(Wattn[(ro + q0) * 8 + hh],     Wattn[(ro + q0 + 1) * 8 + hh],
                       Wattn[(ro + q0 + 8) * 8 + hh], Wattn[(ro + q0 + 9) * 8 + hh]);
    }
    if (i < 24576) {
        int tp = i >> 13, r = i & 8191;
        int fc = r & 3, fr = (r >> 2) & 7, kk = (r >> 5) & 15, g = r >> 9;
        int n = (g >> 2) * 32 + (g & 3) * 8 + fr;
        int k0 = 2 * (kk * 8 + fc);
        const float* W = Wn + (size_t)tp * 32768;
        gBn[i] = pack4(W[k0 * 128 + n],       W[(k0 + 1) * 128 + n],
                       W[(k0 + 8) * 128 + n], W[(k0 + 9) * 128 + n]);
    }
}

// ---------------- single-pass scan with decoupled look-back ----------------
__global__ void k_scan() {
    __shared__ int wsum[8];
    __shared__ int sTotal, sPrefix;
    int b = blockIdx.x, t = threadIdx.x, lane = t & 31, wp = t >> 5;
    int i = b * 256 + t;
    int v = (i < N_NODES) ? g_deg[i] : 0;
    int inc = v;
#pragma unroll
    for (int d = 1; d < 32; d <<= 1) {
        int n = __shfl_up_sync(~0u, inc, d);
        if (lane >= d) inc += n;
    }
    if (lane == 31) wsum[wp] = inc;
    __syncthreads();
    if (t == 0) {
        int r = 0;
        for (int q = 0; q < 8; q++) { int x = wsum[q]; wsum[q] = r; r += x; }
    }
    __syncthreads();
    if (t == 255) sTotal = inc + wsum[wp];   // block total
    __syncthreads();

    if (t == 0 && b == 0) {
        g_pre[0] = sTotal;
        __threadfence();
        g_flag[0] = 2;
        sPrefix = 0;
    }
    if (b > 0) {
        if (t == 0) {
            g_agg[b] = sTotal;
            __threadfence();
            g_flag[b] = 1;
        }
        if (wp == 0) {   // warp 0: parallel look-back
            int prefix = 0;
            int idx = b - 1;
            bool done = false;
            while (!done) {
                int j = idx - lane;
                int f;
                do {
                    f = (j >= 0) ? g_flag[j] : 2;
                } while (__any_sync(0xffffffffu, f == 0));
                int a = 0;
                if (j >= 0) a = (f == 2) ? g_pre[j] : g_agg[j];
                unsigned pm = __ballot_sync(0xffffffffu, f == 2);
                int L = __ffs(pm) - 1;               // pm always nonzero when j<0 lanes exist
                int lim = (pm != 0) ? L : 31;
                int contrib = (lane <= lim) ? a : 0;
#pragma unroll
                for (int d = 16; d; d >>= 1) contrib += __shfl_down_sync(~0u, contrib, d);
                contrib = __shfl_sync(~0u, contrib, 0);
                prefix += contrib;
                if (pm != 0) done = true;
                else idx -= 32;
            }
            if (lane == 0) {
                g_pre[b] = prefix + sTotal;
                __threadfence();
                g_flag[b] = 2;
                sPrefix = prefix;
            }
        }
    }
    __syncthreads();
    int off = sPrefix + inc - v + wsum[wp];
    if (i < N_NODES) { g_off[i] = off; g_cursor[i] = off; }
    if (b == 0 && t == 0) g_off[N_NODES] = N_EDGES;
}

// ---------------- gemm fragment helper (ldmatrix A, contiguous B) ----------------
template <int KSTEPS, int STRIDE>
__device__ __forceinline__ void gemm_frag2(const unsigned* xh, const unsigned* xl,
                                           const uint4* __restrict__ B,
                                           int rb, int nh, int lane, float acc[2][4][4]) {
    int lrow = lane & 15, lhalf = lane >> 4;
    unsigned bh = (unsigned)__cvta_generic_to_shared(xh) + ((rb + lrow) * STRIDE + lhalf * 4) * 4;
    unsigned bl = (unsigned)__cvta_generic_to_shared(xl) + ((rb + lrow) * STRIDE + lhalf * 4) * 4;
    unsigned ch = bh + 32 * STRIDE * 4;
    unsigned cl = bl + 32 * STRIDE * 4;
    const uint4* Bw = B + (nh * 4) * KSTEPS * 32 + lane;
#pragma unroll
    for (int kk = 0; kk < KSTEPS; kk++) {
        unsigned ah0, ah1, ah2, ah3, al0, al1, al2, al3;
        unsigned ch0, ch1, ch2, ch3, cl0, cl1, cl2, cl3;
        ldsm4(ah0, ah1, ah2, ah3, bh + kk * 32);
        ldsm4(al0, al1, al2, al3, bl + kk * 32);
        ldsm4(ch0, ch1, ch2, ch3, ch + kk * 32);
        ldsm4(cl0, cl1, cl2, cl3, cl + kk * 32);
#pragma unroll
        for (int j = 0; j < 4; j++) {
            uint4 b = Bw[(j * KSTEPS + kk) * 32];
            mma16816(acc[0][j], ah0, ah1, ah2, ah3, b.x, b.y);
            mma16816(acc[0][j], ah0, ah1, ah2, ah3, b.z, b.w);
            mma16816(acc[0][j], al0, al1, al2, al3, b.x, b.y);
            mma16816(acc[1][j], ch0, ch1, ch2, ch3, b.x, b.y);
            mma16816(acc[1][j], ch0, ch1, ch2, ch3, b.z, b.w);
            mma16816(acc[1][j], cl0, cl1, cl2, cl3, b.x, b.y);
        }
    }
}

// ---------------- tensor-core node kernel ----------------
#define N_XHI 0
#define N_XLO 8448
#define N_EHI 0
#define N_ELO 4352
#define NODE_SMEM_U32 16896
#define NODE_SMEM_BYTES (NODE_SMEM_U32 * 4)

__global__ void __launch_bounds__(256)
k_node(const float* __restrict__ x) {
    extern __shared__ unsigned su[];
    __shared__ int sNid[64];
    unsigned* Xhi = su + N_XHI;
    unsigned* Xlo = su + N_XLO;
    unsigned* Ehi = su + N_EHI;
    unsigned* Elo = su + N_ELO;

    int t = threadIdx.x, lane = t & 31, w = t >> 5;
    int b = blockIdx.x;
    int tp = b / NBLK64;
    int base = tp * PERM3_CAP + (b - tp * NBLK64) * 64;

    if (g_perm3[base] < 0) return;
    if (t < 64) sNid[t] = g_perm3[base + t];
    __syncthreads();

    {
        int row = t >> 2, seg = t & 3;
        int nid = sNid[row];
        const float4* src = (const float4*)(x + (size_t)(nid < 0 ? 0 : nid) * 256 + seg * 64);
        unsigned* xh = Xhi + row * 132 + seg * 32;
        unsigned* xl = Xlo + row * 132 + seg * 32;
#pragma unroll
        for (int p = 0; p < 16; p++) {
            float4 v = (nid >= 0) ? src[p] : make_float4(0.f, 0.f, 0.f, 0.f);
            unsigned h0, l0, h1, l1;
            splitpack(v.x, v.y, h0, l0);
            splitpack(v.z, v.w, h1, l1);
            xh[p * 2] = h0; xh[p * 2 + 1] = h1;
            xl[p * 2] = l0; xl[p * 2 + 1] = l1;
        }
    }
    __syncthreads();

    int nh = w & 3, rt = w >> 2;
    int rb = rt * 16;
    int fr = lane >> 2, fc = lane & 3;

    float acc[2][4][4];

#pragma unroll
    for (int ti = 0; ti < 2; ti++)
#pragma unroll
        for (int j = 0; j < 4; j++)
#pragma unroll
            for (int c = 0; c < 4; c++) acc[ti][j][c] = 0.f;
    gemm_frag2<16, 132>(Xhi, Xlo, gBn + tp * 8192, rb, nh, lane, acc);
    __syncthreads();
#pragma unroll
    for (int ti = 0; ti < 2; ti++)
#pragma unroll
        for (int j = 0; j < 4; j++) {
            int colu = nh * 16 + j * 4 + fc;
            int r = rb + fr + ti * 32;
            unsigned h, l;
            splitpack(acc[ti][j][0], acc[ti][j][1], h, l);
            Ehi[r * 68 + colu] = h;
            Elo[r * 68 + colu] = l;
            splitpack(acc[ti][j][2], acc[ti][j][3], h, l);
            Ehi[(r + 8) * 68 + colu] = h;
            Elo[(r + 8) * 68 + colu] = l;
        }
    __syncthreads();

#pragma unroll
    for (int ti = 0; ti < 2; ti++)
#pragma unroll
        for (int j = 0; j < 4; j++)
#pragma unroll
            for (int c = 0; c < 4; c++) acc[ti][j][c] = 0.f;
    gemm_frag2<8, 68>(Ehi, Elo, gBuT, rb, nh, lane, acc);
#pragma unroll
    for (int ti = 0; ti < 2; ti++)
#pragma unroll
        for (int j = 0; j < 4; j++) {
            int n0 = nh * 32 + j * 8 + fc * 2;
            int r = rb + fr + ti * 32;
            int n1 = sNid[r], n2 = sNid[r + 8];
            if (n1 >= 0)
                *(float2*)(g_P + (size_t)n1 * 128 + n0) = make_float2(acc[ti][j][0], acc[ti][j][1]);
            if (n2 >= 0)
                *(float2*)(g_P + (size_t)n2 * 128 + n0) = make_float2(acc[ti][j][2], acc[ti][j][3]);
        }

    if (w < 4) {
        int srb = w * 16;
        float sa[2][4];
#pragma unroll
        for (int j = 0; j < 2; j++)
#pragma unroll
            for (int c = 0; c < 4; c++) sa[j][c] = 0.f;
#pragma unroll
        for (int kk = 0; kk < 8; kk++) {
            int o0 = (srb + fr) * 68 + kk * 8 + fc;
            int o1 = o0 + 8 * 68;
            unsigned ah0 = Ehi[o0], ah1 = Ehi[o1], ah2 = Ehi[o0 + 4], ah3 = Ehi[o1 + 4];
            unsigned al0 = Elo[o0], al1 = Elo[o1], al2 = Elo[o0 + 4], al3 = Elo[o1 + 4];
#pragma unroll
            for (int j = 0; j < 2; j++) {
                uint4 bq = gBs[(j * 8 + kk) * 32 + lane];
                mma16816(sa[j], ah0, ah1, ah2, ah3, bq.x, bq.y);
                mma16816(sa[j], ah0, ah1, ah2, ah3, bq.z, bq.w);
                mma16816(sa[j], al0, al1, al2, al3, bq.x, bq.y);
            }
        }
#pragma unroll
        for (int j = 0; j < 2; j++)
#pragma unroll
            for (int q = 0; q < 4; q++) {
                int row = srb + fr + (q >> 1) * 8;
                int nid = sNid[row];
                int h = fc * 2 + (q & 1);
                if (nid >= 0) {
                    if (j == 0) g_star[nid * 8 + h] = sa[j][q];
                    else        g_ssrc[nid * 8 + h] = sa[j][q];
                }
            }
    }
}

// ---------------- tensor-core edge kernel (CSR-position output) ----------------
#define XHI 0
#define XLO 2304
#define AHI 4608
#define ALO 8960
#define THI 13312
#define TLO 0
#define EDGE_SMEM_U32 17664
#define EDGE_SMEM_BYTES (EDGE_SMEM_U32 * 4)

__global__ void __launch_bounds__(256)
k_edge(const float* __restrict__ eattr, const float* __restrict__ etype) {
    extern __shared__ unsigned su[];
    __shared__ int sSrc[ETILE], sTar[ETILE], sPos[ETILE];

    int t = threadIdx.x, lane = t & 31, w = t >> 5;
    int nh = w & 3, rt = w >> 2;
    int rb = rt * 16;
    int fr = lane >> 2, fc = lane & 3;
    int e0 = blockIdx.x * ETILE;

    {
        int row = t >> 2, cg = (t & 3) * 16;
        const float4* src = (const float4*)(eattr + (size_t)(e0 + row) * 64 + cg);
        unsigned* xh = su + XHI + row * 36 + cg / 2;
        unsigned* xl = su + XLO + row * 36 + cg / 2;
#pragma unroll
        for (int p = 0; p < 4; p++) {
            float4 v = src[p];
            unsigned h0, l0, h1, l1;
            splitpack(v.x, v.y, h0, l0);
            splitpack(v.z, v.w, h1, l1);
            xh[p * 2] = h0; xh[p * 2 + 1] = h1;
            xl[p * 2] = l0; xl[p * 2 + 1] = l1;
        }
    }
    if (t < ETILE) {
        int s = g_src[e0 + t];
        sSrc[t] = s;
        sPos[t] = atomicAdd(&g_cursor[s], 1);
    } else if (t < 2 * ETILE) {
        sTar[t - ETILE] = g_tar[e0 + t - ETILE];
    }
    __syncthreads();

    float acc[2][4][4];

    // ---- phase A ----
#pragma unroll
    for (int ti = 0; ti < 2; ti++)
#pragma unroll
        for (int j = 0; j < 4; j++)
#pragma unroll
            for (int c = 0; c < 4; c++) acc[ti][j][c] = 0.f;
    gemm_frag2<4, 36>(su + XHI, su + XLO, gBea, rb, nh, lane, acc);
#pragma unroll
    for (int ti = 0; ti < 2; ti++)
#pragma unroll
        for (int j = 0; j < 4; j++) {
            int colu = nh * 16 + j * 4 + fc;
            int r = rb + fr + ti * 32;
            unsigned h, l;
            splitpack(lrelu(acc[ti][j][0]), lrelu(acc[ti][j][1]), h, l);
            su[AHI + r * 68 + colu] = h;
            su[ALO + r * 68 + colu] = l;
            splitpack(lrelu(acc[ti][j][2]), lrelu(acc[ti][j][3]), h, l);
            su[AHI + (r + 8) * 68 + colu] = h;
            su[ALO + (r + 8) * 68 + colu] = l;
        }
    __syncthreads();

    {
        int row = t >> 2, cg = (t & 3) * 16;
        const float4* src = (const float4*)(etype + (size_t)(e0 + row) * 64 + cg);
        unsigned* xh = su + XHI + row * 36 + cg / 2;
        unsigned* xl = su + XLO + row * 36 + cg / 2;
#pragma unroll
        for (int p = 0; p < 4; p++) {
            float4 v = src[p];
            unsigned h0, l0, h1, l1;
            splitpack(v.x, v.y, h0, l0);
            splitpack(v.z, v.w, h1, l1);
            xh[p * 2] = h0; xh[p * 2 + 1] = h1;
            xl[p * 2] = l0; xl[p * 2 + 1] = l1;
        }
    }
    __syncthreads();

    // ---- phase T (TLO aliases X: sync after gemm reads) ----
#pragma unroll
    for (int ti = 0; ti < 2; ti++)
#pragma unroll
        for (int j = 0; j < 4; j++)
#pragma unroll
            for (int c = 0; c < 4; c++) acc[ti][j][c] = 0.f;
    gemm_frag2<4, 36>(su + XHI, su + XLO, gBet, rb, nh, lane, acc);
    __syncthreads();
#pragma unroll
    for (int ti = 0; ti < 2; ti++)
#pragma unroll
        for (int j = 0; j < 4; j++) {
            int colu = nh * 16 + j * 4 + fc;
            int r = rb + fr + ti * 32;
            unsigned h, l;
            splitpack(lrelu(acc[ti][j][0]), lrelu(acc[ti][j][1]), h, l);
            su[THI + r * 68 + colu] = h;
            su[TLO + r * 68 + colu] = l;
            splitpack(lrelu(acc[ti][j][2]), lrelu(acc[ti][j][3]), h, l);
            su[THI + (r + 8) * 68 + colu] = h;
            su[TLO + (r + 8) * 68 + colu] = l;
        }
    __syncthreads();

    // ---- scores (warps 0-3), ex at CSR position ----
    if (w < 4) {
        int srb = w * 16;
        float sacc[4] = {0.f, 0.f, 0.f, 0.f};
#pragma unroll
        for (int kk = 0; kk < 16; kk++) {
            int base_h = (kk < 8) ? AHI : THI;
            int base_l = (kk < 8) ? ALO : TLO;
            int kx = kk & 7;
            int o0 = (srb + fr) * 68 + kx * 8 + fc;
            int o1 = (srb + fr + 8) * 68 + kx * 8 + fc;
            unsigned ah0 = su[base_h + o0], ah1 = su[base_h + o1];
            unsigned ah2 = su[base_h + o0 + 4], ah3 = su[base_h + o1 + 4];
            unsigned al0 = su[base_l + o0], al1 = su[base_l + o1];
            unsigned al2 = su[base_l + o0 + 4], al3 = su[base_l + o1 + 4];
            uint4 bq = gBa[kk * 32 + lane];
            mma16816(sacc, ah0, ah1, ah2, ah3, bq.x, bq.y);
            mma16816(sacc, ah0, ah1, ah2, ah3, bq.z, bq.w);
            mma16816(sacc, al0, al1, al2, al3, bq.x, bq.y);
        }
        int h0 = fc * 2;
#pragma unroll
        for (int q = 0; q < 4; q++) {
            int row = srb + fr + (q >> 1) * 8;
            int h = h0 + (q & 1);
            int sr = sSrc[row], tg = sTar[row];
            float sc = sacc[q] + g_star[tg * 8 + h] + g_ssrc[sr * 8 + h];
            sc = lrelu(sc);
            float ex = expf(sc);
            g_ex[(size_t)sPos[row] * 8 + h] = ex;
            atomicAdd(&g_denom[sr * 8 + h], ex);
        }
    }

    // ---- phase P (fp16 attrpart at CSR position) ----
#pragma unroll
    for (int ti = 0; ti < 2; ti++)
#pragma unroll
        for (int j = 0; j < 4; j++)
#pragma unroll
            for (int c = 0; c < 4; c++) acc[ti][j][c] = 0.f;
    gemm_frag2<8, 68>(su + AHI, su + ALO, gBup, rb, nh, lane, acc);
#pragma unroll
    for (int ti = 0; ti < 2; ti++)
#pragma unroll
        for (int j = 0; j < 4; j++) {
            int n0 = nh * 32 + j * 8 + fc * 2;
            int r = rb + fr + ti * 32;
            *(__half2*)(g_attrpart_h + (size_t)sPos[r] * 128 + n0) =
                __floats2half2_rn(acc[ti][j][0], acc[ti][j][1]);
            *(__half2*)(g_attrpart_h + (size_t)sPos[r + 8] * 128 + n0) =
                __floats2half2_rn(acc[ti][j][2], acc[ti][j][3]);
        }
}

// ---------------- aggregation: 4 nodes/block, 2 cols/thread (half2) ----------------
__global__ void __launch_bounds__(256)
k_aggr(float* __restrict__ out) {
    int t = threadIdx.x;
    int n = blockIdx.x * 4 + (t >> 6);
    int c = (t & 63) * 2;
    int s = g_off[n], e_end = g_off[n + 1];
    float2 p = *(const float2*)(g_P + (size_t)n * 128 + c);
    float2 acc[8];
#pragma unroll
    for (int h = 0; h < 8; h++) acc[h] = make_float2(0.f, 0.f);
    if (e_end > s) {
        for (int j = s; j < e_end; j++) {
            float2 ap = __half22float2(*(const __half2*)(g_attrpart_h + (size_t)j * 128 + c));
            float mx = lrelu(p.x + ap.x);
            float my = lrelu(p.y + ap.y);
            const float4* xp = (const float4*)(g_ex + (size_t)j * 8);
            float4 ea = xp[0], eb = xp[1];
            acc[0].x += ea.x * mx; acc[0].y += ea.x * my;
            acc[1].x += ea.y * mx; acc[1].y += ea.y * my;
            acc[2].x += ea.z * mx; acc[2].y += ea.z * my;
            acc[3].x += ea.w * mx; acc[3].y += ea.w * my;
            acc[4].x += eb.x * mx; acc[4].y += eb.x * my;
            acc[5].x += eb.y * mx; acc[5].y += eb.y * my;
            acc[6].x += eb.z * mx; acc[6].y += eb.z * my;
            acc[7].x += eb.w * mx; acc[7].y += eb.w * my;
        }
        const float4* dp = (const float4*)(g_denom + n * 8);
        float4 da = dp[0], db = dp[1];
        acc[0].x /= da.x; acc[0].y /= da.x;
        acc[1].x /= da.y; acc[1].y /= da.y;
        acc[2].x /= da.z; acc[2].y /= da.z;
        acc[3].x /= da.w; acc[3].y /= da.w;
        acc[4].x /= db.x; acc[4].y /= db.x;
        acc[5].x /= db.y; acc[5].y /= db.y;
        acc[6].x /= db.z; acc[6].y /= db.z;
        acc[7].x /= db.w; acc[7].y /= db.w;
    }
#pragma unroll
    for (int h = 0; h < 8; h++)
        *(float2*)(out + (size_t)n * 1024 + h * 128 + c) = acc[h];
}

// ---------------- launch (k_node at slot 4 for ncu) ----------------
extern "C" void kernel_launch(void* const* d_in, const int* in_sizes, int n_in,
                              void* d_out, int out_size) {
    const float* node_feats = (const float*)d_in[0];
    const int*   edge_index = (const int*)d_in[1];
    const float* edge_attr  = (const float*)d_in[2];
    const float* edge_type  = (const float*)d_in[3];
    const int*   ntl        = (const int*)d_in[4];
    const float* W_node  = (const float*)d_in[6];
    const float* W_eattr = (const float*)d_in[7];
    const float* W_etype = (const float*)d_in[8];
    const float* W_upd   = (const float*)d_in[9];
    const float* W_attn  = (const float*)d_in[10];
    float* out = (float*)d_out;

    cudaFuncSetAttribute(k_edge, cudaFuncAttributeMaxDynamicSharedMemorySize, EDGE_SMEM_BYTES);
    cudaFuncSetAttribute(k_node, cudaFuncAttributeMaxDynamicSharedMemorySize, NODE_SMEM_BYTES);

    const int TB = 256;
    const int GB_E = (N_EDGES + TB - 1) / TB;

    k_zero<<<GB_E, TB>>>();                                                           // 1
    k_init<<<GB_E, TB>>>(edge_index, ntl, W_eattr, W_etype, W_upd, W_attn, W_node);   // 2
    k_scan<<<NSCANB, TB>>>();                                                         // 3
    k_node<<<3 * NBLK64, TB, NODE_SMEM_BYTES>>>(node_feats);                          // 4 <- profiled
    k_edge<<<NTILES, TB, EDGE_SMEM_BYTES>>>(edge_attr, edge_type);                    // 5
    k_aggr<<<N_NODES / 4, TB>>>(out);                                                 // 6
}

// round 17
// speedup vs baseline: 1.2764x; 1.2764x over previous
#include <cuda_runtime.h>
#include <cuda_fp16.h>
#include <math.h>

#define N_NODES 50000
#define N_EDGES 400000
#define SLOPE   0.2f

#define ETILE   64
#define NTILES  (N_EDGES / ETILE)   // 6250, exact
#define NSCANB  196                 // ceil(50000/256)
#define NBLK64  782                 // ceil(50000/64) tiles per type bucket
#define PERM3_CAP (NBLK64 * 64)     // 50048

// ---------------- scratch ----------------
__device__ __align__(16) float g_P[(size_t)N_NODES * 128];
__device__ __align__(16) float g_star[N_NODES * 8];
__device__ __align__(16) float g_ssrc[N_NODES * 8];
__device__ __align__(16) __half g_attrpart_h[(size_t)N_EDGES * 128];  // CSR-ordered
__device__ __align__(16) float g_ex[N_EDGES * 8];                     // CSR-ordered
__device__ __align__(16) float g_denom[N_NODES * 8];
__device__ int g_src[N_EDGES], g_tar[N_EDGES];
__device__ int g_deg[N_NODES], g_off[N_NODES + 1], g_cursor[N_NODES];
__device__ int g_perm3[3 * PERM3_CAP];
__device__ int g_tcursor3[3];
__device__ volatile int g_agg[NSCANB], g_pre[NSCANB], g_flag[NSCANB];

// mma-ready packed B fragments (fp16 hi/lo), CONTIGUOUS per (warp-group, kstep)
// uint4 {bh0, bh1, bl0, bl1}
__device__ __align__(16) uint4 gBea[16 * 4 * 32];
__device__ __align__(16) uint4 gBet[16 * 4 * 32];
__device__ __align__(16) uint4 gBup[16 * 8 * 32];
__device__ __align__(16) uint4 gBa [16 * 32];
__device__ __align__(16) uint4 gBn [3 * 16 * 16 * 32];
__device__ __align__(16) uint4 gBuT[16 * 8 * 32];
__device__ __align__(16) uint4 gBs [2 * 8 * 32];

__device__ __forceinline__ float lrelu(float x) { return x >= 0.f ? x : SLOPE * x; }

__device__ __forceinline__ unsigned h2u(float x, float y) {
    __half2 h = __floats2half2_rn(x, y);
    return *reinterpret_cast<unsigned*>(&h);
}

// fp16 split of B: hi = fp16(b), lo = fp16(b - hi)
__device__ __forceinline__ uint4 pack4(float w0, float w1, float w2, float w3) {
    float h0 = __half2float(__float2half_rn(w0));
    float h1 = __half2float(__float2half_rn(w1));
    float h2 = __half2float(__float2half_rn(w2));
    float h3 = __half2float(__float2half_rn(w3));
    return make_uint4(h2u(h0, h1), h2u(h2, h3),
                      h2u(w0 - h0, w1 - h1), h2u(w2 - h2, w3 - h3));
}

__device__ __forceinline__ void mma16816(float* c, unsigned a0, unsigned a1, unsigned a2,
                                         unsigned a3, unsigned b0, unsigned b1) {
    asm volatile(
        "mma.sync.aligned.m16n8k16.row.col.f32.f16.f16.f32 "
        "{%0,%1,%2,%3}, {%4,%5,%6,%7}, {%8,%9}, {%0,%1,%2,%3};"
        : "+f"(c[0]), "+f"(c[1]), "+f"(c[2]), "+f"(c[3])
        : "r"(a0), "r"(a1), "r"(a2), "r"(a3), "r"(b0), "r"(b1));
}

__device__ __forceinline__ void ldsm4(unsigned& r0, unsigned& r1, unsigned& r2, unsigned& r3,
                                      unsigned addr) {
    asm volatile("ldmatrix.sync.aligned.m8n8.x4.shared.b16 {%0,%1,%2,%3}, [%4];"
                 : "=r"(r0), "=r"(r1), "=r"(r2), "=r"(r3) : "r"(addr));
}

// ---------------- zeroing ----------------
__global__ void k_zero() {
    int i = blockIdx.x * blockDim.x + threadIdx.x;
    if (i < N_NODES * 8) g_denom[i] = 0.f;
    if (i < N_NODES) g_deg[i] = 0;
    if (i < 3 * PERM3_CAP) g_perm3[i] = -1;
    if (i < 3) g_tcursor3[i] = 0;
    if (i < NSCANB) g_flag[i] = 0;
}

// ---------------- fused init: edge copy + hist + bucket scatter + weight pack ----------------
__global__ void k_init(const int* __restrict__ eidx, const int* __restrict__ ntl,
                       const float* __restrict__ Wea, const float* __restrict__ Wet,
                       const float* __restrict__ Wupd, const float* __restrict__ Wattn,
                       const float* __restrict__ Wn) {
    int i = blockIdx.x * blockDim.x + threadIdx.x;
    if (i < N_EDGES) {
        int s = eidx[i];
        g_src[i] = s;
        g_tar[i] = eidx[N_EDGES + i];
        atomicAdd(&g_deg[s], 1);
    }
    if (i < N_NODES) {
        int tp = ntl[i];
        int p = atomicAdd(&g_tcursor3[tp], 1);
        g_perm3[tp * PERM3_CAP + p] = i;
    }

    if (i < 2048) {
        int fc = i & 3, fr = (i >> 2) & 7, kk = (i >> 5) & 3, g = i >> 7;
        int n = (g >> 2) * 32 + (g & 3) * 8 + fr;
        int k0 = 2 * (kk * 8 + fc);
        gBea[i] = pack4(Wea[k0 * 128 + n],       Wea[(k0 + 1) * 128 + n],
                        Wea[(k0 + 8) * 128 + n], Wea[(k0 + 9) * 128 + n]);
        gBet[i] = pack4(Wet[k0 * 128 + n],       Wet[(k0 + 1) * 128 + n],
                        Wet[(k0 + 8) * 128 + n], Wet[(k0 + 9) * 128 + n]);
    }
    if (i < 4096) {
        int fc = i & 3, fr = (i >> 2) & 7, kk = (i >> 5) & 7, g = i >> 8;
        int n = (g >> 2) * 32 + (g & 3) * 8 + fr;
        int k0 = 2 * (kk * 8 + fc);
        gBup[i] = pack4(Wupd[(128 + k0) * 128 + n], Wupd[(129 + k0) * 128 + n],
                        Wupd[(136 + k0) * 128 + n], Wupd[(137 + k0) * 128 + n]);
        gBuT[i] = pack4(Wupd[k0 * 128 + n],       Wupd[(k0 + 1) * 128 + n],
                        Wupd[(k0 + 8) * 128 + n], Wupd[(k0 + 9) * 128 + n]);
    }
    if (i < 512) {
        int fc = i & 3, fr = (i >> 2) & 7, kk = i >> 5;
        int k0 = 2 * (kk * 8 + fc);
        int h = fr;
        gBa[i] = pack4(Wattn[(128 + k0) * 8 + h], Wattn[(129 + k0) * 8 + h],
                       Wattn[(136 + k0) * 8 + h], Wattn[(137 + k0) * 8 + h]);
        int j = i >> 8, kk2 = (i >> 5) & 7;
        int n = j * 8 + fr;
        int q0 = 2 * (kk2 * 8 + fc);
        int ro = (n < 8) ? 0 : 384;
        int hh = (n < 8) ? n : n - 8;
        gBs[i] = pack4(Wattn[(ro + q0) * 8 + hh],     Wattn[(ro + q0 + 1) * 8 + hh],
                       Wattn[(ro + q0 + 8) * 8 + hh], Wattn[(ro + q0 + 9) * 8 + hh]);
    }
    if (i < 24576) {
        int tp = i >> 13, r = i & 8191;
        int fc = r & 3, fr = (r >> 2) & 7, kk = (r >> 5) & 15, g = r >> 9;
        int n = (g >> 2) * 32 + (g & 3) * 8 + fr;
        int k0 = 2 * (kk * 8 + fc);
        const float* W = Wn + (size_t)tp * 32768;
        gBn[i] = pack4(W[k0 * 128 + n],       W[(k0 + 1) * 128 + n],
                       W[(k0 + 8) * 128 + n], W[(k0 + 9) * 128 + n]);
    }
}

// ---------------- single-pass scan with decoupled look-back ----------------
__global__ void k_scan() {
    __shared__ int wsum[8];
    __shared__ int sTotal, sPrefix;
    int b = blockIdx.x, t = threadIdx.x, lane = t & 31, wp = t >> 5;
    int i = b * 256 + t;
    int v = (i < N_NODES) ? g_deg[i] : 0;
    int inc = v;
#pragma unroll
    for (int d = 1; d < 32; d <<= 1) {
        int n = __shfl_up_sync(~0u, inc, d);
        if (lane >= d) inc += n;
    }
    if (lane == 31) wsum[wp] = inc;
    __syncthreads();
    if (t == 0) {
        int r = 0;
        for (int q = 0; q < 8; q++) { int x = wsum[q]; wsum[q] = r; r += x; }
    }
    __syncthreads();
    if (t == 255) sTotal = inc + wsum[wp];
    __syncthreads();

    if (t == 0 && b == 0) {
        g_pre[0] = sTotal;
        __threadfence();
        g_flag[0] = 2;
        sPrefix = 0;
    }
    if (b > 0) {
        if (t == 0) {
            g_agg[b] = sTotal;
            __threadfence();
            g_flag[b] = 1;
        }
        if (wp == 0) {
            int prefix = 0;
            int idx = b - 1;
            bool done = false;
            while (!done) {
                int j = idx - lane;
                int f;
                do {
                    f = (j >= 0) ? g_flag[j] : 2;
                } while (__any_sync(0xffffffffu, f == 0));
                int a = 0;
                if (j >= 0) a = (f == 2) ? g_pre[j] : g_agg[j];
                unsigned pm = __ballot_sync(0xffffffffu, f == 2);
                int L = __ffs(pm) - 1;
                int lim = (pm != 0) ? L : 31;
                int contrib = (lane <= lim) ? a : 0;
#pragma unroll
                for (int d = 16; d; d >>= 1) contrib += __shfl_down_sync(~0u, contrib, d);
                contrib = __shfl_sync(~0u, contrib, 0);
                prefix += contrib;
                if (pm != 0) done = true;
                else idx -= 32;
            }
            if (lane == 0) {
                g_pre[b] = prefix + sTotal;
                __threadfence();
                g_flag[b] = 2;
                sPrefix = prefix;
            }
        }
    }
    __syncthreads();
    int off = sPrefix + inc - v + wsum[wp];
    if (i < N_NODES) { g_off[i] = off; g_cursor[i] = off; }
    if (b == 0 && t == 0) g_off[N_NODES] = N_EDGES;
}

// ---------------- gemm fragment helper: fp16 A (single), split-fp16 B (2 mma) ----------------
template <int KSTEPS, int STRIDE>
__device__ __forceinline__ void gemm_frag2(const unsigned* xh, const uint4* __restrict__ B,
                                           int rb, int nh, int lane, float acc[2][4][4]) {
    int lrow = lane & 15, lhalf = lane >> 4;
    unsigned bh = (unsigned)__cvta_generic_to_shared(xh) + ((rb + lrow) * STRIDE + lhalf * 4) * 4;
    unsigned ch = bh + 32 * STRIDE * 4;
    const uint4* Bw = B + (nh * 4) * KSTEPS * 32 + lane;
#pragma unroll
    for (int kk = 0; kk < KSTEPS; kk++) {
        unsigned a0, a1, a2, a3, c0, c1, c2, c3;
        ldsm4(a0, a1, a2, a3, bh + kk * 32);
        ldsm4(c0, c1, c2, c3, ch + kk * 32);
#pragma unroll
        for (int j = 0; j < 4; j++) {
            uint4 b = Bw[(j * KSTEPS + kk) * 32];
            mma16816(acc[0][j], a0, a1, a2, a3, b.x, b.y);
            mma16816(acc[0][j], a0, a1, a2, a3, b.z, b.w);
            mma16816(acc[1][j], c0, c1, c2, c3, b.x, b.y);
            mma16816(acc[1][j], c0, c1, c2, c3, b.z, b.w);
        }
    }
}

// ---------------- tensor-core node kernel (fp16, E aliases X) ----------------
#define N_X 0
#define N_E 0                     // aliases X (dead after emb gemm)
#define NODE_SMEM_U32 8448        // X: 64 x 132
#define NODE_SMEM_BYTES (NODE_SMEM_U32 * 4)

__global__ void __launch_bounds__(256, 4)
k_node(const float* __restrict__ x) {
    extern __shared__ unsigned su[];
    __shared__ int sNid[64];
    unsigned* X = su + N_X;   // 64 rows x 128 u32 (256 fp16), stride 132
    unsigned* E = su + N_E;   // 64 rows x 64 u32 (128 fp16), stride 68; aliased

    int t = threadIdx.x, lane = t & 31, w = t >> 5;
    int b = blockIdx.x;
    int tp = b / NBLK64;
    int base = tp * PERM3_CAP + (b - tp * NBLK64) * 64;

    if (g_perm3[base] < 0) return;
    if (t < 64) sNid[t] = g_perm3[base + t];
    __syncthreads();

    {
        int row = t >> 2, seg = t & 3;
        int nid = sNid[row];
        const float4* src = (const float4*)(x + (size_t)(nid < 0 ? 0 : nid) * 256 + seg * 64);
        unsigned* xp = X + row * 132 + seg * 32;
#pragma unroll
        for (int p = 0; p < 16; p++) {
            float4 v = (nid >= 0) ? src[p] : make_float4(0.f, 0.f, 0.f, 0.f);
            xp[p * 2] = h2u(v.x, v.y);
            xp[p * 2 + 1] = h2u(v.z, v.w);
        }
    }
    __syncthreads();

    int nh = w & 3, rt = w >> 2;
    int rb = rt * 16;
    int fr = lane >> 2, fc = lane & 3;

    float acc[2][4][4];

    // emb = X @ Wn[tp]
#pragma unroll
    for (int ti = 0; ti < 2; ti++)
#pragma unroll
        for (int j = 0; j < 4; j++)
#pragma unroll
            for (int c = 0; c < 4; c++) acc[ti][j][c] = 0.f;
    gemm_frag2<16, 132>(X, gBn + tp * 8192, rb, nh, lane, acc);
    __syncthreads();   // X free before E (aliased) written
#pragma unroll
    for (int ti = 0; ti < 2; ti++)
#pragma unroll
        for (int j = 0; j < 4; j++) {
            int colu = nh * 16 + j * 4 + fc;
            int r = rb + fr + ti * 32;
            E[r * 68 + colu] = h2u(acc[ti][j][0], acc[ti][j][1]);
            E[(r + 8) * 68 + colu] = h2u(acc[ti][j][2], acc[ti][j][3]);
        }
    __syncthreads();

    // P = emb @ W_upd[0:128]
#pragma unroll
    for (int ti = 0; ti < 2; ti++)
#pragma unroll
        for (int j = 0; j < 4; j++)
#pragma unroll
            for (int c = 0; c < 4; c++) acc[ti][j][c] = 0.f;
    gemm_frag2<8, 68>(E, gBuT, rb, nh, lane, acc);
#pragma unroll
    for (int ti = 0; ti < 2; ti++)
#pragma unroll
        for (int j = 0; j < 4; j++) {
            int n0 = nh * 32 + j * 8 + fc * 2;
            int r = rb + fr + ti * 32;
            int n1 = sNid[r], n2 = sNid[r + 8];
            if (n1 >= 0)
                *(float2*)(g_P + (size_t)n1 * 128 + n0) = make_float2(acc[ti][j][0], acc[ti][j][1]);
            if (n2 >= 0)
                *(float2*)(g_P + (size_t)n2 * 128 + n0) = make_float2(acc[ti][j][2], acc[ti][j][3]);
        }

    // s_tar / s_src = emb @ Ws (warps 0-3)
    if (w < 4) {
        int srb = w * 16;
        float sa[2][4];
#pragma unroll
        for (int j = 0; j < 2; j++)
#pragma unroll
            for (int c = 0; c < 4; c++) sa[j][c] = 0.f;
#pragma unroll
        for (int kk = 0; kk < 8; kk++) {
            int o0 = (srb + fr) * 68 + kk * 8 + fc;
            int o1 = o0 + 8 * 68;
            unsigned a0 = E[o0], a1 = E[o1], a2 = E[o0 + 4], a3 = E[o1 + 4];
#pragma unroll
            for (int j = 0; j < 2; j++) {
                uint4 bq = gBs[(j * 8 + kk) * 32 + lane];
                mma16816(sa[j], a0, a1, a2, a3, bq.x, bq.y);
                mma16816(sa[j], a0, a1, a2, a3, bq.z, bq.w);
            }
        }
#pragma unroll
        for (int j = 0; j < 2; j++)
#pragma unroll
            for (int q = 0; q < 4; q++) {
                int row = srb + fr + (q >> 1) * 8;
                int nid = sNid[row];
                int h = fc * 2 + (q & 1);
                if (nid >= 0) {
                    if (j == 0) g_star[nid * 8 + h] = sa[j][q];
                    else        g_ssrc[nid * 8 + h] = sa[j][q];
                }
            }
    }
}

// ---------------- tensor-core edge kernel (fp16, no aliasing, 4 syncs) ----------------
#define E_X 0                    // 64 x 36 stride (64 fp16 cols = 32 u32)
#define E_A 2304                 // 64 x 68 stride (128 fp16 cols = 64 u32)
#define E_T 6656
#define EDGE_SMEM_U32 11008
#define EDGE_SMEM_BYTES (EDGE_SMEM_U32 * 4)

__global__ void __launch_bounds__(256, 4)
k_edge(const float* __restrict__ eattr, const float* __restrict__ etype) {
    extern __shared__ unsigned su[];
    __shared__ int sSrc[ETILE], sTar[ETILE], sPos[ETILE];

    int t = threadIdx.x, lane = t & 31, w = t >> 5;
    int nh = w & 3, rt = w >> 2;
    int rb = rt * 16;
    int fr = lane >> 2, fc = lane & 3;
    int e0 = blockIdx.x * ETILE;

    {
        int row = t >> 2, cg = (t & 3) * 16;
        const float4* src = (const float4*)(eattr + (size_t)(e0 + row) * 64 + cg);
        unsigned* xp = su + E_X + row * 36 + cg / 2;
#pragma unroll
        for (int p = 0; p < 4; p++) {
            float4 v = src[p];
            xp[p * 2] = h2u(v.x, v.y);
            xp[p * 2 + 1] = h2u(v.z, v.w);
        }
    }
    if (t < ETILE) {
        int s = g_src[e0 + t];
        sSrc[t] = s;
        sPos[t] = atomicAdd(&g_cursor[s], 1);
    } else if (t < 2 * ETILE) {
        sTar[t - ETILE] = g_tar[e0 + t - ETILE];
    }
    __syncthreads();

    float acc[2][4][4];

    // ---- phase A: A = lrelu(Xa @ Wea) ----
#pragma unroll
    for (int ti = 0; ti < 2; ti++)
#pragma unroll
        for (int j = 0; j < 4; j++)
#pragma unroll
            for (int c = 0; c < 4; c++) acc[ti][j][c] = 0.f;
    gemm_frag2<4, 36>(su + E_X, gBea, rb, nh, lane, acc);
#pragma unroll
    for (int ti = 0; ti < 2; ti++)
#pragma unroll
        for (int j = 0; j < 4; j++) {
            int colu = nh * 16 + j * 4 + fc;
            int r = rb + fr + ti * 32;
            su[E_A + r * 68 + colu] = h2u(lrelu(acc[ti][j][0]), lrelu(acc[ti][j][1]));
            su[E_A + (r + 8) * 68 + colu] = h2u(lrelu(acc[ti][j][2]), lrelu(acc[ti][j][3]));
        }
    __syncthreads();   // A visible; X free

    {
        int row = t >> 2, cg = (t & 3) * 16;
        const float4* src = (const float4*)(etype + (size_t)(e0 + row) * 64 + cg);
        unsigned* xp = su + E_X + row * 36 + cg / 2;
#pragma unroll
        for (int p = 0; p < 4; p++) {
            float4 v = src[p];
            xp[p * 2] = h2u(v.x, v.y);
            xp[p * 2 + 1] = h2u(v.z, v.w);
        }
    }
    __syncthreads();

    // ---- phase T: T = lrelu(Xt @ Wet) ----
#pragma unroll
    for (int ti = 0; ti < 2; ti++)
#pragma unroll
        for (int j = 0; j < 4; j++)
#pragma unroll
            for (int c = 0; c < 4; c++) acc[ti][j][c] = 0.f;
    gemm_frag2<4, 36>(su + E_X, gBet, rb, nh, lane, acc);
#pragma unroll
    for (int ti = 0; ti < 2; ti++)
#pragma unroll
        for (int j = 0; j < 4; j++) {
            int colu = nh * 16 + j * 4 + fc;
            int r = rb + fr + ti * 32;
            su[E_T + r * 68 + colu] = h2u(lrelu(acc[ti][j][0]), lrelu(acc[ti][j][1]));
            su[E_T + (r + 8) * 68 + colu] = h2u(lrelu(acc[ti][j][2]), lrelu(acc[ti][j][3]));
        }
    __syncthreads();

    // ---- scores (warps 0-3), ex at CSR position ----
    if (w < 4) {
        int srb = w * 16;
        float sacc[4] = {0.f, 0.f, 0.f, 0.f};
#pragma unroll
        for (int kk = 0; kk < 16; kk++) {
            int base = (kk < 8) ? E_A : E_T;
            int kx = kk & 7;
            int o0 = (srb + fr) * 68 + kx * 8 + fc;
            int o1 = (srb + fr + 8) * 68 + kx * 8 + fc;
            unsigned a0 = su[base + o0], a1 = su[base + o1];
            unsigned a2 = su[base + o0 + 4], a3 = su[base + o1 + 4];
            uint4 bq = gBa[kk * 32 + lane];
            mma16816(sacc, a0, a1, a2, a3, bq.x, bq.y);
            mma16816(sacc, a0, a1, a2, a3, bq.z, bq.w);
        }
        int h0 = fc * 2;
#pragma unroll
        for (int q = 0; q < 4; q++) {
            int row = srb + fr + (q >> 1) * 8;
            int h = h0 + (q & 1);
            int sr = sSrc[row], tg = sTar[row];
            float sc = sacc[q] + g_star[tg * 8 + h] + g_ssrc[sr * 8 + h];
            sc = lrelu(sc);
            float ex = expf(sc);
            g_ex[(size_t)sPos[row] * 8 + h] = ex;
            atomicAdd(&g_denom[sr * 8 + h], ex);
        }
    }

    // ---- phase P: attrpart (fp16) at CSR position ----
#pragma unroll
    for (int ti = 0; ti < 2; ti++)
#pragma unroll
        for (int j = 0; j < 4; j++)
#pragma unroll
            for (int c = 0; c < 4; c++) acc[ti][j][c] = 0.f;
    gemm_frag2<8, 68>(su + E_A, gBup, rb, nh, lane, acc);
#pragma unroll
    for (int ti = 0; ti < 2; ti++)
#pragma unroll
        for (int j = 0; j < 4; j++) {
            int n0 = nh * 32 + j * 8 + fc * 2;
            int r = rb + fr + ti * 32;
            *(__half2*)(g_attrpart_h + (size_t)sPos[r] * 128 + n0) =
                __floats2half2_rn(acc[ti][j][0], acc[ti][j][1]);
            *(__half2*)(g_attrpart_h + (size_t)sPos[r + 8] * 128 + n0) =
                __floats2half2_rn(acc[ti][j][2], acc[ti][j][3]);
        }
}

// ---------------- aggregation: 4 nodes/block, 2 cols/thread (half2) ----------------
__global__ void __launch_bounds__(256)
k_aggr(float* __restrict__ out) {
    int t = threadIdx.x;
    int n = blockIdx.x * 4 + (t >> 6);
    int c = (t & 63) * 2;
    int s = g_off[n], e_end = g_off[n + 1];
    float2 p = *(const float2*)(g_P + (size_t)n * 128 + c);
    float2 acc[8];
#pragma unroll
    for (int h = 0; h < 8; h++) acc[h] = make_float2(0.f, 0.f);
    if (e_end > s) {
        for (int j = s; j < e_end; j++) {
            float2 ap = __half22float2(*(const __half2*)(g_attrpart_h + (size_t)j * 128 + c));
            float mx = lrelu(p.x + ap.x);
            float my = lrelu(p.y + ap.y);
            const float4* xp = (const float4*)(g_ex + (size_t)j * 8);
            float4 ea = xp[0], eb = xp[1];
            acc[0].x += ea.x * mx; acc[0].y += ea.x * my;
            acc[1].x += ea.y * mx; acc[1].y += ea.y * my;
            acc[2].x += ea.z * mx; acc[2].y += ea.z * my;
            acc[3].x += ea.w * mx; acc[3].y += ea.w * my;
            acc[4].x += eb.x * mx; acc[4].y += eb.x * my;
            acc[5].x += eb.y * mx; acc[5].y += eb.y * my;
            acc[6].x += eb.z * mx; acc[6].y += eb.z * my;
            acc[7].x += eb.w * mx; acc[7].y += eb.w * my;
        }
        const float4* dp = (const float4*)(g_denom + n * 8);
        float4 da = dp[0], db = dp[1];
        acc[0].x /= da.x; acc[0].y /= da.x;
        acc[1].x /= da.y; acc[1].y /= da.y;
        acc[2].x /= da.z; acc[2].y /= da.z;
        acc[3].x /= da.w; acc[3].y /= da.w;
        acc[4].x /= db.x; acc[4].y /= db.x;
        acc[5].x /= db.y; acc[5].y /= db.y;
        acc[6].x /= db.z; acc[6].y /= db.z;
        acc[7].x /= db.w; acc[7].y /= db.w;
    }
#pragma unroll
    for (int h = 0; h < 8; h++)
        *(float2*)(out + (size_t)n * 1024 + h * 128 + c) = acc[h];
}

// ---------------- launch (k_node at slot 4 for ncu control) ----------------
extern "C" void kernel_launch(void* const* d_in, const int* in_sizes, int n_in,
                              void* d_out, int out_size) {
    const float* node_feats = (const float*)d_in[0];
    const int*   edge_index = (const int*)d_in[1];
    const float* edge_attr  = (const float*)d_in[2];
    const float* edge_type  = (const float*)d_in[3];
    const int*   ntl        = (const int*)d_in[4];
    const float* W_node  = (const float*)d_in[6];
    const float* W_eattr = (const float*)d_in[7];
    const float* W_etype = (const float*)d_in[8];
    const float* W_upd   = (const float*)d_in[9];
    const float* W_attn  = (const float*)d_in[10];
    float* out = (float*)d_out;

    cudaFuncSetAttribute(k_edge, cudaFuncAttributeMaxDynamicSharedMemorySize, EDGE_SMEM_BYTES);
    cudaFuncSetAttribute(k_node, cudaFuncAttributeMaxDynamicSharedMemorySize, NODE_SMEM_BYTES);

    const int TB = 256;
    const int GB_E = (N_EDGES + TB - 1) / TB;

    k_zero<<<GB_E, TB>>>();                                                           // 1
    k_init<<<GB_E, TB>>>(edge_index, ntl, W_eattr, W_etype, W_upd, W_attn, W_node);   // 2
    k_scan<<<NSCANB, TB>>>();                                                         // 3
    k_node<<<3 * NBLK64, TB, NODE_SMEM_BYTES>>>(node_feats);                          // 4 <- profiled
    k_edge<<<NTILES, TB, EDGE_SMEM_BYTES>>>(edge_attr, edge_type);                    // 5
    k_aggr<<<N_NODES / 4, TB>>>(out);                                                 // 6
}